// round 13
// baseline (speedup 1.0000x reference)
#include <cuda_runtime.h>
#include <math.h>

#define BB 64
#define TT 512
#define DD 512
#define HH 1024

#define NCTA 128
#define NTHR 512
#define NWARP 16
#define JB   8
#define KSL  64                      // k-slice per warp

#define NRCH 8                       // rows per staged chunk
#define NCHR (BB / NRCH)             // 8 chunks per step
#define HRS  1028                    // staged row stride (floats), 16B-multiple
#define HBUF_FLOATS (NRCH * HRS)     // 8224 per buffer

// partials: [g][w][b][j] = 3*16*64*8 floats (96 KB)
#define PART_FLOATS (3 * NWARP * BB * JB)
#define SMEM_FLOATS (PART_FLOATS + 2 * HBUF_FLOATS)
#define SMEM_BYTES (SMEM_FLOATS * 4)

typedef unsigned long long u64;

// Scratch (static device globals — allocation-free kernel_launch)
__device__ float g_XG[3 * TT * BB * HH];   // [g][t][b][h] x-projections (+ input bias)
__device__ float g_h[2][BB * HH];          // ping-pong hidden state
__device__ unsigned int g_bar_count = 0;
__device__ unsigned int g_bar_gen = 0;

__device__ __forceinline__ void ffma2(u64& d, u64 a, u64 b) {
    asm("fma.rn.f32x2 %0, %1, %2, %0;" : "+l"(d) : "l"(a), "l"(b));
}
__device__ __forceinline__ float pairsum(u64 v) {
    return __uint_as_float((unsigned)(v & 0xffffffffull)) +
           __uint_as_float((unsigned)(v >> 32));
}
__device__ __forceinline__ u64 pack2(float lo, float hi) {
    u64 r;
    asm("mov.b64 %0, {%1, %2};" : "=l"(r) : "f"(lo), "f"(hi));
    return r;
}
__device__ __forceinline__ u64 splat2(float a) {
    u64 r;
    asm("mov.b64 %0, {%1, %1};" : "=l"(r) : "f"(a));
    return r;
}
__device__ __forceinline__ unsigned smem_u32(const void* p) {
    return (unsigned)__cvta_generic_to_shared(p);
}
// 16B async copy global->smem, L1-bypass (.cg) — h produced by other SMs.
__device__ __forceinline__ void cp_async16(unsigned dst, const void* src) {
    asm volatile("cp.async.cg.shared.global [%0], [%1], 16;" :: "r"(dst), "l"(src));
}
__device__ __forceinline__ void cp_commit() {
    asm volatile("cp.async.commit_group;");
}
template <int N>
__device__ __forceinline__ void cp_wait() {
    asm volatile("cp.async.wait_group %0;" :: "n"(N));
}

// All 128 CTAs co-resident (1 CTA/SM) -> spin barrier safe. acq/rel semantics.
__device__ __forceinline__ void grid_barrier() {
    __syncthreads();
    if (threadIdx.x == 0) {
        unsigned gen;
        asm volatile("ld.relaxed.gpu.global.u32 %0, [%1];" : "=r"(gen) : "l"(&g_bar_gen));
        unsigned old;
        asm volatile("atom.acq_rel.gpu.global.add.u32 %0, [%1], 1;" : "=r"(old) : "l"(&g_bar_count));
        if (old == NCTA - 1) {
            asm volatile("st.relaxed.gpu.global.u32 [%0], %1;" :: "l"(&g_bar_count), "r"(0u));
            asm volatile("st.release.gpu.global.u32 [%0], %1;" :: "l"(&g_bar_gen), "r"(gen + 1));
        } else {
            unsigned cur;
            do {
                asm volatile("ld.acquire.gpu.global.u32 %0, [%1];" : "=r"(cur) : "l"(&g_bar_gen));
            } while (cur == gen);
        }
    }
    __syncthreads();
}

// ---------------------------------------------------------------------------
// Precompute xg[g][t][b][:] = x[b][t][:] @ W_gx + b_gx  (128x128x16, FFMA2)
// ---------------------------------------------------------------------------
__global__ __launch_bounds__(256) void xproj_kernel(
    const float* __restrict__ x,
    const float* __restrict__ Wz, const float* __restrict__ Wr, const float* __restrict__ Wn,
    const float* __restrict__ bz, const float* __restrict__ br, const float* __restrict__ bn) {

    int g = blockIdx.z;
    const float* Wm   = (g == 0) ? Wz : ((g == 1) ? Wr : Wn);
    const float* bias = (g == 0) ? bz : ((g == 1) ? br : bn);

    __shared__ float As[16][128];   // [k][m]
    __shared__ float Bs[16][128];   // [k][n]

    int m0 = blockIdx.x * 128;
    int n0 = blockIdx.y * 128;
    int tid = threadIdx.x;
    int txq = tid % 16, tyq = tid / 16;

    u64 acc2[4][8];
#pragma unroll
    for (int i = 0; i < 4; i++)
#pragma unroll
        for (int j = 0; j < 8; j++) acc2[i][j] = 0ull;

    for (int k0 = 0; k0 < DD; k0 += 16) {
#pragma unroll
        for (int l = 0; l < 2; l++) {
            int idx = tid + l * 256;
            int row = idx >> 2;
            int kk  = (idx & 3) * 4;
            float4 v = *(const float4*)&x[(size_t)(m0 + row) * DD + k0 + kk];
            As[kk + 0][row] = v.x;
            As[kk + 1][row] = v.y;
            As[kk + 2][row] = v.z;
            As[kk + 3][row] = v.w;
        }
#pragma unroll
        for (int l = 0; l < 2; l++) {
            int idx = tid + l * 256;
            int row = idx >> 5;
            int nn  = (idx & 31) * 4;
            *(float4*)&Bs[row][nn] = *(const float4*)&Wm[(size_t)(k0 + row) * HH + n0 + nn];
        }
        __syncthreads();
#pragma unroll
        for (int k = 0; k < 16; k++) {
            const u64* Ap = (const u64*)&As[k][tyq * 8];
            u64 ap0 = Ap[0], ap1 = Ap[1], ap2 = Ap[2], ap3 = Ap[3];
            float4 b0 = *(const float4*)&Bs[k][txq * 8];
            float4 b1 = *(const float4*)&Bs[k][txq * 8 + 4];
            u64 bs[8];
            bs[0] = splat2(b0.x); bs[1] = splat2(b0.y); bs[2] = splat2(b0.z); bs[3] = splat2(b0.w);
            bs[4] = splat2(b1.x); bs[5] = splat2(b1.y); bs[6] = splat2(b1.z); bs[7] = splat2(b1.w);
#pragma unroll
            for (int j = 0; j < 8; j++) {
                ffma2(acc2[0][j], ap0, bs[j]);
                ffma2(acc2[1][j], ap1, bs[j]);
                ffma2(acc2[2][j], ap2, bs[j]);
                ffma2(acc2[3][j], ap3, bs[j]);
            }
        }
        __syncthreads();
    }

#pragma unroll
    for (int ip = 0; ip < 4; ip++) {
#pragma unroll
        for (int half = 0; half < 2; half++) {
            int m  = m0 + tyq * 8 + ip * 2 + half;
            int bbv = m / TT;
            int tt = m % TT;
            float* outr = &g_XG[(((size_t)g * TT + tt) * BB + bbv) * HH + n0 + txq * 8];
#pragma unroll
            for (int j = 0; j < 8; j++) {
                u64 v = acc2[ip][j];
                float f = half ? __uint_as_float((unsigned)(v >> 32))
                               : __uint_as_float((unsigned)(v & 0xffffffffull));
                outr[j] = f + bias[n0 + txq * 8 + j];
            }
        }
    }
}

// ---------------------------------------------------------------------------
// Persistent GRU scan: register-resident W, 16 warps (4/SMSP), k split across
// warps. Warp w owns k[64w, 64w+64); lane=(j=l&7, ksub=l>>3); thread holds
// W[3][16k] in 24 u64 regs. Same 1:6 LDS:FFMA2 ratio as the 8-warp winner,
// but 4 warps/SMSP hide the shfl-reduce tail and LDS latency.
// Conflict-free interleave: ksub s owns float4s {s, s+4, s+8, s+12} of the
// warp's 16-float4 slice.
// ---------------------------------------------------------------------------
__global__ __launch_bounds__(NTHR, 1) void gru_scan_kernel(
    float* __restrict__ out,
    const float* __restrict__ Wzh, const float* __restrict__ Wrh, const float* __restrict__ Wnh,
    const float* __restrict__ bzh, const float* __restrict__ brh, const float* __restrict__ bnh)
{
    extern __shared__ float smem[];
    float* part = smem;                      // [g][w][b][j]: g*8192 + w*512 + b*8 + j
    float* hbuf0 = smem + PART_FLOATS;
    float* hbuf1 = hbuf0 + HBUF_FLOATS;

    const int tid  = threadIdx.x;
    const int jbk  = blockIdx.x;
    const int warp = tid >> 5;
    const int lane = tid & 31;
    const int jl   = lane & 7;
    const int ksub = lane >> 3;                 // 0..3
    const int kwb  = warp * KSL;                // warp's k-slice base
    const int pbase = warp * 512 + jl;          // partial store base

    // ---- W into registers, permuted k order (held for all 512 steps) ----
    // pair p (=2i+half, i=0..3): k = kwb + (ksub + 4i)*4 + half*2
    u64 wz[8], wr[8], wn[8];
    {
        const int jcolw = jbk * JB + jl;
#pragma unroll
        for (int p = 0; p < 8; p++) {
            int i    = p >> 1;
            int half = p & 1;
            int k    = kwb + (ksub + 4 * i) * 4 + half * 2;
            wz[p] = pack2(__ldg(&Wzh[(size_t)k * HH + jcolw]), __ldg(&Wzh[(size_t)(k + 1) * HH + jcolw]));
            wr[p] = pack2(__ldg(&Wrh[(size_t)k * HH + jcolw]), __ldg(&Wrh[(size_t)(k + 1) * HH + jcolw]));
            wn[p] = pack2(__ldg(&Wnh[(size_t)k * HH + jcolw]), __ldg(&Wnh[(size_t)(k + 1) * HH + jcolw]));
        }
    }

    // ---- epilogue constants: thread handles output (b = tid>>3, j = tid&7) ----
    const int bq = tid >> 3;
    const int jq = tid & 7;
    const int jc = jbk * JB + jq;
    const float bzv = __ldg(&bzh[jc]);
    const float brv = __ldg(&brh[jc]);
    const float bnv = __ldg(&bnh[jc]);

    // ---- zero h[0] (disjoint slices) ----
    for (int e = tid; e < (BB * HH) / NCTA; e += NTHR)
        g_h[0][blockIdx.x * ((BB * HH) / NCTA) + e] = 0.0f;
    grid_barrier();

    // staging: chunk = 8 rows x 1024 floats = 2048 float4; thread copies 4.
    // idx = tid + l*512 in [0,2048): row = idx>>8 (0..7), col4 = idx&255.
#define STAGE(BUF, CH) do {                                                        \
        float* buf_ = (BUF);                                                       \
        const float* hsrc_ = h_in + (size_t)((CH) * NRCH) * HH;                    \
        _Pragma("unroll")                                                          \
        for (int l_ = 0; l_ < 4; l_++) {                                           \
            int idx_ = tid + l_ * NTHR;                                            \
            int row_ = idx_ >> 8;                                                  \
            int col_ = (idx_ & 255) * 4;                                           \
            cp_async16(smem_u32(&buf_[row_ * HRS + col_]),                         \
                       &hsrc_[(size_t)row_ * HH + col_]);                          \
        }                                                                          \
        cp_commit();                                                               \
    } while (0)

    // conflict-free: 4 s-lanes read adjacent float4s (16B apart), 8 j broadcast
#define LDSROW(BUF, SRC, LR) do {                                                  \
        const float4* hp4_ = (const float4*)((SRC) + (LR) * HRS + kwb);            \
        _Pragma("unroll")                                                          \
        for (int i_ = 0; i_ < 4; i_++) (BUF)[i_] = hp4_[ksub + 4 * i_];            \
    } while (0)

#define GRU_BODY(BUF, BV) do {                                                     \
        u64 az_ = 0, ar_ = 0, an_ = 0;                                             \
        const u64* hp_ = (const u64*)(BUF);                                        \
        _Pragma("unroll")                                                          \
        for (int p_ = 0; p_ < 8; p_++) {                                           \
            ffma2(az_, hp_[p_], wz[p_]);                                           \
            ffma2(ar_, hp_[p_], wr[p_]);                                           \
            ffma2(an_, hp_[p_], wn[p_]);                                           \
        }                                                                          \
        float zz_ = pairsum(az_), rr_ = pairsum(ar_), nn_ = pairsum(an_);          \
        zz_ += __shfl_xor_sync(0xffffffffu, zz_, 8);                               \
        zz_ += __shfl_xor_sync(0xffffffffu, zz_, 16);                              \
        rr_ += __shfl_xor_sync(0xffffffffu, rr_, 8);                               \
        rr_ += __shfl_xor_sync(0xffffffffu, rr_, 16);                              \
        nn_ += __shfl_xor_sync(0xffffffffu, nn_, 8);                               \
        nn_ += __shfl_xor_sync(0xffffffffu, nn_, 16);                              \
        if (ksub == 0) {                                                           \
            part[pbase + (BV) * 8]         = zz_;                                  \
            part[pbase + (BV) * 8 + 8192]  = rr_;                                  \
            part[pbase + (BV) * 8 + 16384] = nn_;                                  \
        }                                                                          \
    } while (0)

    for (int t = 0; t < TT; t++) {
        const float* __restrict__ h_in  = g_h[t & 1];
        float* __restrict__ h_out = (t == TT - 1) ? out : g_h[(t + 1) & 1];

        // epilogue operand prefetch (consumed after the row loop)
        const float* xz = g_XG + ((size_t)(0 * TT + t)) * (BB * HH);
        const float* xr = g_XG + ((size_t)(1 * TT + t)) * (BB * HH);
        const float* xn = g_XG + ((size_t)(2 * TT + t)) * (BB * HH);
        float xzp = __ldg(&xz[(size_t)bq * HH + jc]);
        float xrp = __ldg(&xr[(size_t)bq * HH + jc]);
        float xnp = __ldg(&xn[(size_t)bq * HH + jc]);
        float hpv = __ldcg(&h_in[(size_t)bq * HH + jc]);

        // prologue: stage chunk 0
        STAGE(hbuf0, 0);

        for (int ch = 0; ch < NCHR; ch++) {
            float* cur = (ch & 1) ? hbuf1 : hbuf0;
            if (ch + 1 < NCHR) {
                STAGE(((ch + 1) & 1) ? hbuf1 : hbuf0, ch + 1);
                cp_wait<1>();
            } else {
                cp_wait<0>();
            }
            __syncthreads();     // chunk ch visible to all threads

            // consume 8 rows, software-pipelined LDS by 2
            float4 bufA[4], bufB[4];
            LDSROW(bufA, cur, 0);
#pragma unroll
            for (int r = 0; r < NRCH; r += 2) {
                LDSROW(bufB, cur, r + 1);
                GRU_BODY(bufA, ch * NRCH + r);
                if (r + 2 < NRCH) LDSROW(bufA, cur, r + 2);
                GRU_BODY(bufB, ch * NRCH + r + 1);
            }
            __syncthreads();     // cur free for the chunk after next
        }

        // ---- cross-warp reduce + gate epilogue (1 output per thread) ----
        {
            const int o = bq * 8 + jq;
            float sz = 0.0f, sr = 0.0f, sn = 0.0f;
#pragma unroll
            for (int w = 0; w < NWARP; w++) {
                sz += part[w * 512 + o];
                sr += part[8192 + w * 512 + o];
                sn += part[16384 + w * 512 + o];
            }
            float z = 1.0f / (1.0f + __expf(-(xzp + sz + bzv)));
            float r = 1.0f / (1.0f + __expf(-(xrp + sr + brv)));
            float n = tanhf(xnp + r * (sn + bnv));
            __stcg(&h_out[(size_t)bq * HH + jc], (1.0f - z) * n + z * hpv);
        }

        if (t != TT - 1) grid_barrier();
    }
#undef STAGE
#undef LDSROW
#undef GRU_BODY
}

// ---------------------------------------------------------------------------
extern "C" void kernel_launch(void* const* d_in, const int* in_sizes, int n_in,
                              void* d_out, int out_size) {
    const float* x    = (const float*)d_in[0];
    const float* W_zx = (const float*)d_in[1];
    const float* W_zh = (const float*)d_in[2];
    const float* W_rx = (const float*)d_in[3];
    const float* W_rh = (const float*)d_in[4];
    const float* W_nx = (const float*)d_in[5];
    const float* W_nh = (const float*)d_in[6];
    const float* b_zx = (const float*)d_in[7];
    const float* b_zh = (const float*)d_in[8];
    const float* b_rx = (const float*)d_in[9];
    const float* b_rh = (const float*)d_in[10];
    const float* b_nx = (const float*)d_in[11];
    const float* b_nh = (const float*)d_in[12];
    float* out = (float*)d_out;

    cudaFuncSetAttribute(gru_scan_kernel,
                         cudaFuncAttributeMaxDynamicSharedMemorySize, SMEM_BYTES);

    xproj_kernel<<<dim3((BB * TT) / 128, HH / 128, 3), 256>>>(
        x, W_zx, W_rx, W_nx, b_zx, b_rx, b_nx);

    gru_scan_kernel<<<NCTA, NTHR, SMEM_BYTES>>>(
        out, W_zh, W_rh, W_nh, b_zh, b_rh, b_nh);
}

// round 14
// speedup vs baseline: 1.1113x; 1.1113x over previous
#include <cuda_runtime.h>
#include <math.h>

#define BB 64
#define TT 512
#define DD 512
#define HH 1024

#define NCTA 128
#define NTHR 256
#define JB   8

#define NRCH 16                      // rows per staged chunk
#define NCHR (BB / NRCH)             // 4 chunks per step
#define HRS  1028                    // staged h row stride (floats)
#define HBUF_FLOATS (NRCH * HRS)     // 16448 per buffer

// partials: [g][wh][b][j], wh = warp*2+half (16), padded stride 520
#define WHS 520
#define PART_FLOATS (3 * 16 * WHS)   // 24960
#define SMEM_FLOATS (PART_FLOATS + 2 * HBUF_FLOATS)
#define SMEM_BYTES (SMEM_FLOATS * 4) // 231,424 B  (< 232,448 max)

typedef unsigned long long u64;

// Scratch (static device globals — allocation-free kernel_launch)
__device__ float g_XG[3 * TT * BB * HH];   // [g][t][b][h] x-projections (+ input bias)
__device__ float g_h[2][BB * HH];          // ping-pong hidden state
__device__ unsigned int g_bar_count = 0;
__device__ unsigned int g_bar_gen = 0;

__device__ __forceinline__ void ffma2(u64& d, u64 a, u64 b) {
    asm("fma.rn.f32x2 %0, %1, %2, %0;" : "+l"(d) : "l"(a), "l"(b));
}
__device__ __forceinline__ float pairsum(u64 v) {
    return __uint_as_float((unsigned)(v & 0xffffffffull)) +
           __uint_as_float((unsigned)(v >> 32));
}
__device__ __forceinline__ u64 pack2(float lo, float hi) {
    u64 r;
    asm("mov.b64 %0, {%1, %2};" : "=l"(r) : "f"(lo), "f"(hi));
    return r;
}
__device__ __forceinline__ u64 splat2(float a) {
    u64 r;
    asm("mov.b64 %0, {%1, %1};" : "=l"(r) : "f"(a));
    return r;
}
__device__ __forceinline__ unsigned smem_u32(const void* p) {
    return (unsigned)__cvta_generic_to_shared(p);
}
// 16B async copy global->smem, L1-bypass (.cg) — h produced by other SMs.
__device__ __forceinline__ void cp_async16(unsigned dst, const void* src) {
    asm volatile("cp.async.cg.shared.global [%0], [%1], 16;" :: "r"(dst), "l"(src));
}
__device__ __forceinline__ void cp_commit() {
    asm volatile("cp.async.commit_group;");
}
template <int N>
__device__ __forceinline__ void cp_wait() {
    asm volatile("cp.async.wait_group %0;" :: "n"(N));
}

// All 128 CTAs co-resident (1 CTA/SM) -> spin barrier safe. acq/rel semantics.
__device__ __forceinline__ void grid_barrier() {
    __syncthreads();
    if (threadIdx.x == 0) {
        unsigned gen;
        asm volatile("ld.relaxed.gpu.global.u32 %0, [%1];" : "=r"(gen) : "l"(&g_bar_gen));
        unsigned old;
        asm volatile("atom.acq_rel.gpu.global.add.u32 %0, [%1], 1;" : "=r"(old) : "l"(&g_bar_count));
        if (old == NCTA - 1) {
            asm volatile("st.relaxed.gpu.global.u32 [%0], %1;" :: "l"(&g_bar_count), "r"(0u));
            asm volatile("st.release.gpu.global.u32 [%0], %1;" :: "l"(&g_bar_gen), "r"(gen + 1));
        } else {
            unsigned cur;
            do {
                asm volatile("ld.acquire.gpu.global.u32 %0, [%1];" : "=r"(cur) : "l"(&g_bar_gen));
            } while (cur == gen);
        }
    }
    __syncthreads();
}

// ---------------------------------------------------------------------------
// Precompute xg[g][t][b][:] = x[b][t][:] @ W_gx + b_gx  (128x128x16, FFMA2)
// ---------------------------------------------------------------------------
__global__ __launch_bounds__(256) void xproj_kernel(
    const float* __restrict__ x,
    const float* __restrict__ Wz, const float* __restrict__ Wr, const float* __restrict__ Wn,
    const float* __restrict__ bz, const float* __restrict__ br, const float* __restrict__ bn) {

    int g = blockIdx.z;
    const float* Wm   = (g == 0) ? Wz : ((g == 1) ? Wr : Wn);
    const float* bias = (g == 0) ? bz : ((g == 1) ? br : bn);

    __shared__ float As[16][128];   // [k][m]
    __shared__ float Bs[16][128];   // [k][n]

    int m0 = blockIdx.x * 128;
    int n0 = blockIdx.y * 128;
    int tid = threadIdx.x;
    int txq = tid % 16, tyq = tid / 16;

    u64 acc2[4][8];
#pragma unroll
    for (int i = 0; i < 4; i++)
#pragma unroll
        for (int j = 0; j < 8; j++) acc2[i][j] = 0ull;

    for (int k0 = 0; k0 < DD; k0 += 16) {
#pragma unroll
        for (int l = 0; l < 2; l++) {
            int idx = tid + l * 256;
            int row = idx >> 2;
            int kk  = (idx & 3) * 4;
            float4 v = *(const float4*)&x[(size_t)(m0 + row) * DD + k0 + kk];
            As[kk + 0][row] = v.x;
            As[kk + 1][row] = v.y;
            As[kk + 2][row] = v.z;
            As[kk + 3][row] = v.w;
        }
#pragma unroll
        for (int l = 0; l < 2; l++) {
            int idx = tid + l * 256;
            int row = idx >> 5;
            int nn  = (idx & 31) * 4;
            *(float4*)&Bs[row][nn] = *(const float4*)&Wm[(size_t)(k0 + row) * HH + n0 + nn];
        }
        __syncthreads();
#pragma unroll
        for (int k = 0; k < 16; k++) {
            const u64* Ap = (const u64*)&As[k][tyq * 8];
            u64 ap0 = Ap[0], ap1 = Ap[1], ap2 = Ap[2], ap3 = Ap[3];
            float4 b0 = *(const float4*)&Bs[k][txq * 8];
            float4 b1 = *(const float4*)&Bs[k][txq * 8 + 4];
            u64 bs[8];
            bs[0] = splat2(b0.x); bs[1] = splat2(b0.y); bs[2] = splat2(b0.z); bs[3] = splat2(b0.w);
            bs[4] = splat2(b1.x); bs[5] = splat2(b1.y); bs[6] = splat2(b1.z); bs[7] = splat2(b1.w);
#pragma unroll
            for (int j = 0; j < 8; j++) {
                ffma2(acc2[0][j], ap0, bs[j]);
                ffma2(acc2[1][j], ap1, bs[j]);
                ffma2(acc2[2][j], ap2, bs[j]);
                ffma2(acc2[3][j], ap3, bs[j]);
            }
        }
        __syncthreads();
    }

#pragma unroll
    for (int ip = 0; ip < 4; ip++) {
#pragma unroll
        for (int half = 0; half < 2; half++) {
            int m  = m0 + tyq * 8 + ip * 2 + half;
            int bbv = m / TT;
            int tt = m % TT;
            float* outr = &g_XG[(((size_t)g * TT + tt) * BB + bbv) * HH + n0 + txq * 8];
#pragma unroll
            for (int j = 0; j < 8; j++) {
                u64 v = acc2[ip][j];
                float f = half ? __uint_as_float((unsigned)(v >> 32))
                               : __uint_as_float((unsigned)(v & 0xffffffffull));
                outr[j] = f + bias[n0 + txq * 8 + j];
            }
        }
    }
}

// ---------------------------------------------------------------------------
// Persistent GRU scan (R12 geometry): 8 warps, register-resident W,
// cp.async h staging, conflict-free k interleave. New in this round:
//   * 2-row fused body — 96 FFMA2 over 6 independent chains
//   * 1-round shfl reduce (xor 8); ksub 0 and 2 store two partials per
//     (warp,row,j); epilogue sums 16 partials (padded stride, conflict-free)
// ---------------------------------------------------------------------------
__global__ __launch_bounds__(NTHR, 1) void gru_scan_kernel(
    float* __restrict__ out,
    const float* __restrict__ Wzh, const float* __restrict__ Wrh, const float* __restrict__ Wnh,
    const float* __restrict__ bzh, const float* __restrict__ brh, const float* __restrict__ bnh)
{
    extern __shared__ float smem[];
    float* part = smem;                      // [g][wh][row*8+j] stride WHS
    float* hbuf0 = smem + PART_FLOATS;
    float* hbuf1 = hbuf0 + HBUF_FLOATS;

    const int tid  = threadIdx.x;
    const int jbk  = blockIdx.x;
    const int warp = tid >> 5;
    const int lane = tid & 31;
    const int jl   = lane & 7;
    const int ksub = lane >> 3;                 // 0..3
    const int kwb  = warp * 128;                // warp's k-slice base
    // partial store base: [g][warp*2 + (ksub>>1)][b*8 + jl]
    const int pbase = (warp * 2 + (ksub >> 1)) * WHS + jl;
    const bool pstore = (ksub & 1) == 0;

    // ---- W into registers, permuted k order (held for all 512 steps) ----
    // pair p (=2i+half): k = kwb + (ksub + 4i)*4 + half*2
    u64 wz[16], wr[16], wn[16];
    {
        const int jcolw = jbk * JB + jl;
#pragma unroll
        for (int p = 0; p < 16; p++) {
            int i    = p >> 1;
            int half = p & 1;
            int k    = kwb + (ksub + 4 * i) * 4 + half * 2;
            wz[p] = pack2(__ldg(&Wzh[(size_t)k * HH + jcolw]), __ldg(&Wzh[(size_t)(k + 1) * HH + jcolw]));
            wr[p] = pack2(__ldg(&Wrh[(size_t)k * HH + jcolw]), __ldg(&Wrh[(size_t)(k + 1) * HH + jcolw]));
            wn[p] = pack2(__ldg(&Wnh[(size_t)k * HH + jcolw]), __ldg(&Wnh[(size_t)(k + 1) * HH + jcolw]));
        }
    }

    // ---- epilogue constants: thread handles output pairs tid, tid+256 ----
    int bq[2], jq[2], jc[2];
    float bzv[2], brv[2], bnv[2];
#pragma unroll
    for (int q = 0; q < 2; q++) {
        int p = tid + q * 256;
        bq[q] = p >> 3;
        jq[q] = p & 7;
        jc[q] = jbk * JB + jq[q];
        bzv[q] = __ldg(&bzh[jc[q]]);
        brv[q] = __ldg(&brh[jc[q]]);
        bnv[q] = __ldg(&bnh[jc[q]]);
    }

    // ---- zero h[0] (disjoint slices) ----
    for (int e = tid; e < (BB * HH) / NCTA; e += NTHR)
        g_h[0][blockIdx.x * ((BB * HH) / NCTA) + e] = 0.0f;
    grid_barrier();

    // staging: chunk = 16 rows x 1024 floats = 4096 float4; thread copies 16.
#define STAGE(BUF, CH) do {                                                        \
        float* buf_ = (BUF);                                                       \
        const float* hsrc_ = h_in + (size_t)((CH) * NRCH) * HH;                    \
        _Pragma("unroll")                                                          \
        for (int l_ = 0; l_ < 16; l_++) {                                          \
            int idx_ = tid + l_ * NTHR;                                            \
            int row_ = idx_ >> 8;                                                  \
            int col_ = (idx_ & 255) * 4;                                           \
            cp_async16(smem_u32(&buf_[row_ * HRS + col_]),                         \
                       &hsrc_[(size_t)row_ * HH + col_]);                          \
        }                                                                          \
        cp_commit();                                                               \
    } while (0)

    // conflict-free: 4 s-lanes read adjacent float4s (16B apart), 8 j broadcast
#define LDSROW(BUF, SRC, LR) do {                                                  \
        const float4* hp4_ = (const float4*)((SRC) + (LR) * HRS + kwb);            \
        _Pragma("unroll")                                                          \
        for (int i_ = 0; i_ < 8; i_++) (BUF)[i_] = hp4_[ksub + 4 * i_];            \
    } while (0)

    // two rows fused: 6 independent FFMA2 chains; 1-round shfl; 2-half partials
#define GRU_BODY2(BUFA, BUFB, BVA, BVB) do {                                       \
        u64 azA_ = 0, arA_ = 0, anA_ = 0, azB_ = 0, arB_ = 0, anB_ = 0;            \
        const u64* ha_ = (const u64*)(BUFA);                                       \
        const u64* hb_ = (const u64*)(BUFB);                                       \
        _Pragma("unroll")                                                          \
        for (int p_ = 0; p_ < 16; p_++) {                                          \
            ffma2(azA_, ha_[p_], wz[p_]); ffma2(azB_, hb_[p_], wz[p_]);            \
            ffma2(arA_, ha_[p_], wr[p_]); ffma2(arB_, hb_[p_], wr[p_]);            \
            ffma2(anA_, ha_[p_], wn[p_]); ffma2(anB_, hb_[p_], wn[p_]);            \
        }                                                                          \
        float zA_ = pairsum(azA_), rA_ = pairsum(arA_), nA_ = pairsum(anA_);       \
        float zB_ = pairsum(azB_), rB_ = pairsum(arB_), nB_ = pairsum(anB_);       \
        zA_ += __shfl_xor_sync(0xffffffffu, zA_, 8);                               \
        rA_ += __shfl_xor_sync(0xffffffffu, rA_, 8);                               \
        nA_ += __shfl_xor_sync(0xffffffffu, nA_, 8);                               \
        zB_ += __shfl_xor_sync(0xffffffffu, zB_, 8);                               \
        rB_ += __shfl_xor_sync(0xffffffffu, rB_, 8);                               \
        nB_ += __shfl_xor_sync(0xffffffffu, nB_, 8);                               \
        if (pstore) {                                                              \
            part[pbase + (BVA) * 8]             = zA_;                             \
            part[pbase + (BVA) * 8 + 16 * WHS]  = rA_;                             \
            part[pbase + (BVA) * 8 + 32 * WHS]  = nA_;                             \
            part[pbase + (BVB) * 8]             = zB_;                             \
            part[pbase + (BVB) * 8 + 16 * WHS]  = rB_;                             \
            part[pbase + (BVB) * 8 + 32 * WHS]  = nB_;                             \
        }                                                                          \
    } while (0)

    for (int t = 0; t < TT; t++) {
        const float* __restrict__ h_in  = g_h[t & 1];
        float* __restrict__ h_out = (t == TT - 1) ? out : g_h[(t + 1) & 1];

        // epilogue operand prefetch (consumed after the row loop)
        const float* xz = g_XG + ((size_t)(0 * TT + t)) * (BB * HH);
        const float* xr = g_XG + ((size_t)(1 * TT + t)) * (BB * HH);
        const float* xn = g_XG + ((size_t)(2 * TT + t)) * (BB * HH);
        float xzp[2], xrp[2], xnp[2], hpv[2];
#pragma unroll
        for (int q = 0; q < 2; q++) {
            xzp[q] = __ldg(&xz[(size_t)bq[q] * HH + jc[q]]);
            xrp[q] = __ldg(&xr[(size_t)bq[q] * HH + jc[q]]);
            xnp[q] = __ldg(&xn[(size_t)bq[q] * HH + jc[q]]);
            hpv[q] = __ldcg(&h_in[(size_t)bq[q] * HH + jc[q]]);
        }

        // prologue: stage chunk 0
        STAGE(hbuf0, 0);

        for (int ch = 0; ch < NCHR; ch++) {
            float* cur = (ch & 1) ? hbuf1 : hbuf0;
            if (ch + 1 < NCHR) {
                STAGE(((ch + 1) & 1) ? hbuf1 : hbuf0, ch + 1);
                cp_wait<1>();
            } else {
                cp_wait<0>();
            }
            __syncthreads();     // chunk ch visible to all threads

            // consume 16 rows, two at a time
            float4 bufA[8], bufB[8];
#pragma unroll
            for (int r = 0; r < NRCH; r += 2) {
                LDSROW(bufA, cur, r);
                LDSROW(bufB, cur, r + 1);
                GRU_BODY2(bufA, bufB, ch * NRCH + r, ch * NRCH + r + 1);
            }
            __syncthreads();     // cur free for the chunk after next
        }

        // ---- cross-warp reduce (16 halves) + gate epilogue ----
#pragma unroll
        for (int q = 0; q < 2; q++) {
            int o = bq[q] * 8 + jq[q];
            float sz = 0.0f, sr = 0.0f, sn = 0.0f;
#pragma unroll
            for (int w = 0; w < 16; w++) {
                sz += part[w * WHS + o];
                sr += part[16 * WHS + w * WHS + o];
                sn += part[32 * WHS + w * WHS + o];
            }
            float z = 1.0f / (1.0f + __expf(-(xzp[q] + sz + bzv[q])));
            float r = 1.0f / (1.0f + __expf(-(xrp[q] + sr + brv[q])));
            float n = tanhf(xnp[q] + r * (sn + bnv[q]));
            __stcg(&h_out[(size_t)bq[q] * HH + jc[q]], (1.0f - z) * n + z * hpv[q]);
        }

        if (t != TT - 1) grid_barrier();
    }
#undef STAGE
#undef LDSROW
#undef GRU_BODY2
}

// ---------------------------------------------------------------------------
extern "C" void kernel_launch(void* const* d_in, const int* in_sizes, int n_in,
                              void* d_out, int out_size) {
    const float* x    = (const float*)d_in[0];
    const float* W_zx = (const float*)d_in[1];
    const float* W_zh = (const float*)d_in[2];
    const float* W_rx = (const float*)d_in[3];
    const float* W_rh = (const float*)d_in[4];
    const float* W_nx = (const float*)d_in[5];
    const float* W_nh = (const float*)d_in[6];
    const float* b_zx = (const float*)d_in[7];
    const float* b_zh = (const float*)d_in[8];
    const float* b_rx = (const float*)d_in[9];
    const float* b_rh = (const float*)d_in[10];
    const float* b_nx = (const float*)d_in[11];
    const float* b_nh = (const float*)d_in[12];
    float* out = (float*)d_out;

    cudaFuncSetAttribute(gru_scan_kernel,
                         cudaFuncAttributeMaxDynamicSharedMemorySize, SMEM_BYTES);

    xproj_kernel<<<dim3((BB * TT) / 128, HH / 128, 3), 256>>>(
        x, W_zx, W_rx, W_nx, b_zx, b_rx, b_nx);

    gru_scan_kernel<<<NCTA, NTHR, SMEM_BYTES>>>(
        out, W_zh, W_rh, W_nh, b_zh, b_rh, b_nh);
}

// round 15
// speedup vs baseline: 1.1432x; 1.0288x over previous
#include <cuda_runtime.h>
#include <math.h>

#define BB 64
#define TT 512
#define DD 512
#define HH 1024

#define NCTA 128
#define NTHR 256
#define JB   8

#define NRCH 16                      // rows per staged chunk
#define NCHR (BB / NRCH)             // 4 chunks per step
#define HRS  1028                    // staged h row stride (floats)
#define HBUF_FLOATS (NRCH * HRS)     // 16448 per buffer

// partials: [g][wh][b][j], wh = warp*2+half (16), padded stride 520
#define WHS 520
#define PART_FLOATS (3 * 16 * WHS)   // 24960
#define SMEM_FLOATS (PART_FLOATS + 2 * HBUF_FLOATS)
#define SMEM_BYTES (SMEM_FLOATS * 4) // 231,424 B

typedef unsigned long long u64;

// Scratch (static device globals — allocation-free kernel_launch)
__device__ float g_XG[3 * TT * BB * HH];   // [g][t][b][h] x-projections (+ input bias)
__device__ float g_h[2][BB * HH];          // ping-pong hidden state
__device__ unsigned int g_count;           // monotonic barrier counter (reset per launch)

__device__ __forceinline__ void ffma2(u64& d, u64 a, u64 b) {
    asm("fma.rn.f32x2 %0, %1, %2, %0;" : "+l"(d) : "l"(a), "l"(b));
}
__device__ __forceinline__ float pairsum(u64 v) {
    return __uint_as_float((unsigned)(v & 0xffffffffull)) +
           __uint_as_float((unsigned)(v >> 32));
}
__device__ __forceinline__ u64 pack2(float lo, float hi) {
    u64 r;
    asm("mov.b64 %0, {%1, %2};" : "=l"(r) : "f"(lo), "f"(hi));
    return r;
}
__device__ __forceinline__ u64 splat2(float a) {
    u64 r;
    asm("mov.b64 %0, {%1, %1};" : "=l"(r) : "f"(a));
    return r;
}
__device__ __forceinline__ unsigned smem_u32(const void* p) {
    return (unsigned)__cvta_generic_to_shared(p);
}
// 16B async copy global->smem, L1-bypass (.cg) — h produced by other SMs.
__device__ __forceinline__ void cp_async16(unsigned dst, const void* src) {
    asm volatile("cp.async.cg.shared.global [%0], [%1], 16;" :: "r"(dst), "l"(src));
}
__device__ __forceinline__ void cp_commit() {
    asm volatile("cp.async.commit_group;");
}
template <int N>
__device__ __forceinline__ void cp_wait() {
    asm volatile("cp.async.wait_group %0;" :: "n"(N));
}

// Fast grid barrier: REDG (no-return, ~0.854 cyc/op at LTS) + monotonic
// acquire-poll against epoch*NCTA. Counter reset per launch by reset_kernel.
// All 128 CTAs co-resident (1 CTA/SM) -> spin is safe.
__device__ __forceinline__ void grid_barrier_fast(unsigned target) {
    __syncthreads();
    if (threadIdx.x == 0) {
        asm volatile("red.release.gpu.global.add.u32 [%0], 1;" :: "l"(&g_count));
        unsigned v;
        do {
            asm volatile("ld.acquire.gpu.global.u32 %0, [%1];" : "=r"(v) : "l"(&g_count));
        } while (v < target);
    }
    __syncthreads();
}

// ---------------------------------------------------------------------------
__global__ void reset_kernel() {
    if (threadIdx.x == 0) g_count = 0;
}

// ---------------------------------------------------------------------------
// Precompute xg[g][t][b][:] = x[b][t][:] @ W_gx + b_gx  (128x128x16, FFMA2)
// ---------------------------------------------------------------------------
__global__ __launch_bounds__(256) void xproj_kernel(
    const float* __restrict__ x,
    const float* __restrict__ Wz, const float* __restrict__ Wr, const float* __restrict__ Wn,
    const float* __restrict__ bz, const float* __restrict__ br, const float* __restrict__ bn) {

    int g = blockIdx.z;
    const float* Wm   = (g == 0) ? Wz : ((g == 1) ? Wr : Wn);
    const float* bias = (g == 0) ? bz : ((g == 1) ? br : bn);

    __shared__ float As[16][128];   // [k][m]
    __shared__ float Bs[16][128];   // [k][n]

    int m0 = blockIdx.x * 128;
    int n0 = blockIdx.y * 128;
    int tid = threadIdx.x;
    int txq = tid % 16, tyq = tid / 16;

    u64 acc2[4][8];
#pragma unroll
    for (int i = 0; i < 4; i++)
#pragma unroll
        for (int j = 0; j < 8; j++) acc2[i][j] = 0ull;

    for (int k0 = 0; k0 < DD; k0 += 16) {
#pragma unroll
        for (int l = 0; l < 2; l++) {
            int idx = tid + l * 256;
            int row = idx >> 2;
            int kk  = (idx & 3) * 4;
            float4 v = *(const float4*)&x[(size_t)(m0 + row) * DD + k0 + kk];
            As[kk + 0][row] = v.x;
            As[kk + 1][row] = v.y;
            As[kk + 2][row] = v.z;
            As[kk + 3][row] = v.w;
        }
#pragma unroll
        for (int l = 0; l < 2; l++) {
            int idx = tid + l * 256;
            int row = idx >> 5;
            int nn  = (idx & 31) * 4;
            *(float4*)&Bs[row][nn] = *(const float4*)&Wm[(size_t)(k0 + row) * HH + n0 + nn];
        }
        __syncthreads();
#pragma unroll
        for (int k = 0; k < 16; k++) {
            const u64* Ap = (const u64*)&As[k][tyq * 8];
            u64 ap0 = Ap[0], ap1 = Ap[1], ap2 = Ap[2], ap3 = Ap[3];
            float4 b0 = *(const float4*)&Bs[k][txq * 8];
            float4 b1 = *(const float4*)&Bs[k][txq * 8 + 4];
            u64 bs[8];
            bs[0] = splat2(b0.x); bs[1] = splat2(b0.y); bs[2] = splat2(b0.z); bs[3] = splat2(b0.w);
            bs[4] = splat2(b1.x); bs[5] = splat2(b1.y); bs[6] = splat2(b1.z); bs[7] = splat2(b1.w);
#pragma unroll
            for (int j = 0; j < 8; j++) {
                ffma2(acc2[0][j], ap0, bs[j]);
                ffma2(acc2[1][j], ap1, bs[j]);
                ffma2(acc2[2][j], ap2, bs[j]);
                ffma2(acc2[3][j], ap3, bs[j]);
            }
        }
        __syncthreads();
    }

#pragma unroll
    for (int ip = 0; ip < 4; ip++) {
#pragma unroll
        for (int half = 0; half < 2; half++) {
            int m  = m0 + tyq * 8 + ip * 2 + half;
            int bbv = m / TT;
            int tt = m % TT;
            float* outr = &g_XG[(((size_t)g * TT + tt) * BB + bbv) * HH + n0 + txq * 8];
#pragma unroll
            for (int j = 0; j < 8; j++) {
                u64 v = acc2[ip][j];
                float f = half ? __uint_as_float((unsigned)(v >> 32))
                               : __uint_as_float((unsigned)(v & 0xffffffffull));
                outr[j] = f + bias[n0 + txq * 8 + j];
            }
        }
    }
}

// ---------------------------------------------------------------------------
// Persistent GRU scan (R14 winner + fast REDG barrier):
// 8 warps, register-resident W, cp.async h staging, conflict-free k
// interleave, 2-row fused body, 1-round shfl reduce, 16-partial epilogue.
// ---------------------------------------------------------------------------
__global__ __launch_bounds__(NTHR, 1) void gru_scan_kernel(
    float* __restrict__ out,
    const float* __restrict__ Wzh, const float* __restrict__ Wrh, const float* __restrict__ Wnh,
    const float* __restrict__ bzh, const float* __restrict__ brh, const float* __restrict__ bnh)
{
    extern __shared__ float smem[];
    float* part = smem;                      // [g][wh][row*8+j] stride WHS
    float* hbuf0 = smem + PART_FLOATS;
    float* hbuf1 = hbuf0 + HBUF_FLOATS;

    const int tid  = threadIdx.x;
    const int jbk  = blockIdx.x;
    const int warp = tid >> 5;
    const int lane = tid & 31;
    const int jl   = lane & 7;
    const int ksub = lane >> 3;                 // 0..3
    const int kwb  = warp * 128;                // warp's k-slice base
    const int pbase = (warp * 2 + (ksub >> 1)) * WHS + jl;
    const bool pstore = (ksub & 1) == 0;

    // ---- W into registers, permuted k order (held for all 512 steps) ----
    u64 wz[16], wr[16], wn[16];
    {
        const int jcolw = jbk * JB + jl;
#pragma unroll
        for (int p = 0; p < 16; p++) {
            int i    = p >> 1;
            int half = p & 1;
            int k    = kwb + (ksub + 4 * i) * 4 + half * 2;
            wz[p] = pack2(__ldg(&Wzh[(size_t)k * HH + jcolw]), __ldg(&Wzh[(size_t)(k + 1) * HH + jcolw]));
            wr[p] = pack2(__ldg(&Wrh[(size_t)k * HH + jcolw]), __ldg(&Wrh[(size_t)(k + 1) * HH + jcolw]));
            wn[p] = pack2(__ldg(&Wnh[(size_t)k * HH + jcolw]), __ldg(&Wnh[(size_t)(k + 1) * HH + jcolw]));
        }
    }

    // ---- epilogue constants: thread handles output pairs tid, tid+256 ----
    int bq[2], jq[2], jc[2];
    float bzv[2], brv[2], bnv[2];
#pragma unroll
    for (int q = 0; q < 2; q++) {
        int p = tid + q * 256;
        bq[q] = p >> 3;
        jq[q] = p & 7;
        jc[q] = jbk * JB + jq[q];
        bzv[q] = __ldg(&bzh[jc[q]]);
        brv[q] = __ldg(&brh[jc[q]]);
        bnv[q] = __ldg(&bnh[jc[q]]);
    }

    // ---- zero h[0] (disjoint slices) ----
    for (int e = tid; e < (BB * HH) / NCTA; e += NTHR)
        g_h[0][blockIdx.x * ((BB * HH) / NCTA) + e] = 0.0f;
    unsigned epoch = 1;
    grid_barrier_fast(epoch * NCTA);

#define STAGE(BUF, CH) do {                                                        \
        float* buf_ = (BUF);                                                       \
        const float* hsrc_ = h_in + (size_t)((CH) * NRCH) * HH;                    \
        _Pragma("unroll")                                                          \
        for (int l_ = 0; l_ < 16; l_++) {                                          \
            int idx_ = tid + l_ * NTHR;                                            \
            int row_ = idx_ >> 8;                                                  \
            int col_ = (idx_ & 255) * 4;                                           \
            cp_async16(smem_u32(&buf_[row_ * HRS + col_]),                         \
                       &hsrc_[(size_t)row_ * HH + col_]);                          \
        }                                                                          \
        cp_commit();                                                               \
    } while (0)

#define LDSROW(BUF, SRC, LR) do {                                                  \
        const float4* hp4_ = (const float4*)((SRC) + (LR) * HRS + kwb);            \
        _Pragma("unroll")                                                          \
        for (int i_ = 0; i_ < 8; i_++) (BUF)[i_] = hp4_[ksub + 4 * i_];            \
    } while (0)

#define GRU_BODY2(BUFA, BUFB, BVA, BVB) do {                                       \
        u64 azA_ = 0, arA_ = 0, anA_ = 0, azB_ = 0, arB_ = 0, anB_ = 0;            \
        const u64* ha_ = (const u64*)(BUFA);                                       \
        const u64* hb_ = (const u64*)(BUFB);                                       \
        _Pragma("unroll")                                                          \
        for (int p_ = 0; p_ < 16; p_++) {                                          \
            ffma2(azA_, ha_[p_], wz[p_]); ffma2(azB_, hb_[p_], wz[p_]);            \
            ffma2(arA_, ha_[p_], wr[p_]); ffma2(arB_, hb_[p_], wr[p_]);            \
            ffma2(anA_, ha_[p_], wn[p_]); ffma2(anB_, hb_[p_], wn[p_]);            \
        }                                                                          \
        float zA_ = pairsum(azA_), rA_ = pairsum(arA_), nA_ = pairsum(anA_);       \
        float zB_ = pairsum(azB_), rB_ = pairsum(arB_), nB_ = pairsum(anB_);       \
        zA_ += __shfl_xor_sync(0xffffffffu, zA_, 8);                               \
        rA_ += __shfl_xor_sync(0xffffffffu, rA_, 8);                               \
        nA_ += __shfl_xor_sync(0xffffffffu, nA_, 8);                               \
        zB_ += __shfl_xor_sync(0xffffffffu, zB_, 8);                               \
        rB_ += __shfl_xor_sync(0xffffffffu, rB_, 8);                               \
        nB_ += __shfl_xor_sync(0xffffffffu, nB_, 8);                               \
        if (pstore) {                                                              \
            part[pbase + (BVA) * 8]             = zA_;                             \
            part[pbase + (BVA) * 8 + 16 * WHS]  = rA_;                             \
            part[pbase + (BVA) * 8 + 32 * WHS]  = nA_;                             \
            part[pbase + (BVB) * 8]             = zB_;                             \
            part[pbase + (BVB) * 8 + 16 * WHS]  = rB_;                             \
            part[pbase + (BVB) * 8 + 32 * WHS]  = nB_;                             \
        }                                                                          \
    } while (0)

    for (int t = 0; t < TT; t++) {
        const float* __restrict__ h_in  = g_h[t & 1];
        float* __restrict__ h_out = (t == TT - 1) ? out : g_h[(t + 1) & 1];

        // epilogue operand prefetch (consumed after the row loop)
        const float* xz = g_XG + ((size_t)(0 * TT + t)) * (BB * HH);
        const float* xr = g_XG + ((size_t)(1 * TT + t)) * (BB * HH);
        const float* xn = g_XG + ((size_t)(2 * TT + t)) * (BB * HH);
        float xzp[2], xrp[2], xnp[2], hpv[2];
#pragma unroll
        for (int q = 0; q < 2; q++) {
            xzp[q] = __ldg(&xz[(size_t)bq[q] * HH + jc[q]]);
            xrp[q] = __ldg(&xr[(size_t)bq[q] * HH + jc[q]]);
            xnp[q] = __ldg(&xn[(size_t)bq[q] * HH + jc[q]]);
            hpv[q] = __ldcg(&h_in[(size_t)bq[q] * HH + jc[q]]);
        }

        // prologue: stage chunk 0
        STAGE(hbuf0, 0);

        for (int ch = 0; ch < NCHR; ch++) {
            float* cur = (ch & 1) ? hbuf1 : hbuf0;
            if (ch + 1 < NCHR) {
                STAGE(((ch + 1) & 1) ? hbuf1 : hbuf0, ch + 1);
                cp_wait<1>();
            } else {
                cp_wait<0>();
            }
            __syncthreads();     // chunk ch visible to all threads

            // consume 16 rows, two at a time
            float4 bufA[8], bufB[8];
#pragma unroll
            for (int r = 0; r < NRCH; r += 2) {
                LDSROW(bufA, cur, r);
                LDSROW(bufB, cur, r + 1);
                GRU_BODY2(bufA, bufB, ch * NRCH + r, ch * NRCH + r + 1);
            }
            __syncthreads();     // cur free for the chunk after next
        }

        // ---- cross-warp reduce (16 halves) + gate epilogue ----
#pragma unroll
        for (int q = 0; q < 2; q++) {
            int o = bq[q] * 8 + jq[q];
            float sz = 0.0f, sr = 0.0f, sn = 0.0f;
#pragma unroll
            for (int w = 0; w < 16; w++) {
                sz += part[w * WHS + o];
                sr += part[16 * WHS + w * WHS + o];
                sn += part[32 * WHS + w * WHS + o];
            }
            float z = 1.0f / (1.0f + __expf(-(xzp[q] + sz + bzv[q])));
            float r = 1.0f / (1.0f + __expf(-(xrp[q] + sr + brv[q])));
            float n = tanhf(xnp[q] + r * (sn + bnv[q]));
            __stcg(&h_out[(size_t)bq[q] * HH + jc[q]], (1.0f - z) * n + z * hpv[q]);
        }

        if (t != TT - 1) {
            ++epoch;
            grid_barrier_fast(epoch * NCTA);
        }
    }
#undef STAGE
#undef LDSROW
#undef GRU_BODY2
}

// ---------------------------------------------------------------------------
extern "C" void kernel_launch(void* const* d_in, const int* in_sizes, int n_in,
                              void* d_out, int out_size) {
    const float* x    = (const float*)d_in[0];
    const float* W_zx = (const float*)d_in[1];
    const float* W_zh = (const float*)d_in[2];
    const float* W_rx = (const float*)d_in[3];
    const float* W_rh = (const float*)d_in[4];
    const float* W_nx = (const float*)d_in[5];
    const float* W_nh = (const float*)d_in[6];
    const float* b_zx = (const float*)d_in[7];
    const float* b_zh = (const float*)d_in[8];
    const float* b_rx = (const float*)d_in[9];
    const float* b_rh = (const float*)d_in[10];
    const float* b_nx = (const float*)d_in[11];
    const float* b_nh = (const float*)d_in[12];
    float* out = (float*)d_out;

    cudaFuncSetAttribute(gru_scan_kernel,
                         cudaFuncAttributeMaxDynamicSharedMemorySize, SMEM_BYTES);

    reset_kernel<<<1, 32>>>();
    xproj_kernel<<<dim3((BB * TT) / 128, HH / 128, 3), 256>>>(
        x, W_zx, W_rx, W_nx, b_zx, b_rx, b_nx);
    gru_scan_kernel<<<NCTA, NTHR, SMEM_BYTES>>>(
        out, W_zh, W_rh, W_nh, b_zh, b_rh, b_nh);
}

// round 17
// speedup vs baseline: 1.1534x; 1.0089x over previous
#include <cuda_runtime.h>
#include <cuda_bf16.h>
#include <math.h>
#include <stdint.h>

#define BB 64
#define TT 512
#define DD 512
#define HH 1024

#define NCTA 128
#define NTHR 256
#define JB   8

// ---- scan smem layout ----
#define NST  26                         // partial n-stride (floats)
#define WSTR (64 * NST)                 // per-warp partial stride = 1664
#define PART_FLOATS (8 * WSTR)          // 13312 floats = 53248 B
#define SM_A_OFF (PART_FLOATS * 4)      // 53248
#define AST   2064                      // staged A row stride (bytes): 2048+16, conflict-free
#define A_COMP (16 * AST)               // 33024 B (16 rows, one precision comp)
#define A_BUF  (2 * A_COMP)             // 66048 B (hi+lo)
#define SCAN_SMEM (SM_A_OFF + 2 * A_BUF)   // 185344 B

typedef unsigned long long u64;

// ---- device globals ----
__device__ float g_XG[3 * TT * BB * HH];       // [g][t][b][h]
__device__ float g_hf[2][BB * HH];             // fp32 h ping-pong (epilogue-exact)
__device__ __nv_bfloat16 g_hhi[2][BB * HH];    // h hi split (mma input)
__device__ __nv_bfloat16 g_hlo[2][BB * HH];    // h lo split (mma input)
__device__ unsigned int g_count;               // barrier counter (reset per launch)

// ---- helpers ----
__device__ __forceinline__ void ffma2(u64& d, u64 a, u64 b) {
    asm("fma.rn.f32x2 %0, %1, %2, %0;" : "+l"(d) : "l"(a), "l"(b));
}
__device__ __forceinline__ u64 splat2(float a) {
    u64 r; asm("mov.b64 %0, {%1, %1};" : "=l"(r) : "f"(a)); return r;
}
__device__ __forceinline__ unsigned smem_u32(const void* p) {
    return (unsigned)__cvta_generic_to_shared(p);
}
__device__ __forceinline__ void cp_async16(unsigned dst, const void* src) {
    asm volatile("cp.async.cg.shared.global [%0], [%1], 16;" :: "r"(dst), "l"(src));
}
__device__ __forceinline__ void cp_commit() { asm volatile("cp.async.commit_group;"); }
template <int N> __device__ __forceinline__ void cp_wait() {
    asm volatile("cp.async.wait_group %0;" :: "n"(N));
}
__device__ __forceinline__ void ldmat4(unsigned* r, uint32_t addr) {
    asm volatile("ldmatrix.sync.aligned.m8n8.x4.shared.b16 {%0,%1,%2,%3}, [%4];"
                 : "=r"(r[0]), "=r"(r[1]), "=r"(r[2]), "=r"(r[3]) : "r"(addr));
}
__device__ __forceinline__ void mma_bf16(float* d, const unsigned* a, const unsigned* b) {
    asm volatile(
        "mma.sync.aligned.m16n8k16.row.col.f32.bf16.bf16.f32 "
        "{%0,%1,%2,%3}, {%4,%5,%6,%7}, {%8,%9}, {%0,%1,%2,%3};"
        : "+f"(d[0]), "+f"(d[1]), "+f"(d[2]), "+f"(d[3])
        : "r"(a[0]), "r"(a[1]), "r"(a[2]), "r"(a[3]), "r"(b[0]), "r"(b[1]));
}
__device__ __forceinline__ unsigned pkbf(__nv_bfloat16 a, __nv_bfloat16 b) {
    return (unsigned)__bfloat16_as_ushort(a) | ((unsigned)__bfloat16_as_ushort(b) << 16);
}
__device__ __forceinline__ void stcg_u16(__nv_bfloat16* p, __nv_bfloat16 v) {
    unsigned short u = __bfloat16_as_ushort(v);
    asm volatile("st.global.cg.u16 [%0], %1;" :: "l"(p), "h"(u));
}

// fast grid barrier: REDG + monotonic acquire-poll
__device__ __forceinline__ void grid_barrier_fast(unsigned target) {
    __syncthreads();
    if (threadIdx.x == 0) {
        asm volatile("red.release.gpu.global.add.u32 [%0], 1;" :: "l"(&g_count));
        unsigned v;
        do { asm volatile("ld.acquire.gpu.global.u32 %0, [%1];" : "=r"(v) : "l"(&g_count)); }
        while (v < target);
    }
    __syncthreads();
}

__global__ void reset_kernel() { if (threadIdx.x == 0) g_count = 0; }

// ---------------------------------------------------------------------------
// xproj: xg[g][t][b][:] = x[b][t][:] @ W_gx + b_gx  (128x128x16, FFMA2)
// ---------------------------------------------------------------------------
__global__ __launch_bounds__(256) void xproj_kernel(
    const float* __restrict__ x,
    const float* __restrict__ Wz, const float* __restrict__ Wr, const float* __restrict__ Wn,
    const float* __restrict__ bz, const float* __restrict__ br, const float* __restrict__ bn) {

    int g = blockIdx.z;
    const float* Wm   = (g == 0) ? Wz : ((g == 1) ? Wr : Wn);
    const float* bias = (g == 0) ? bz : ((g == 1) ? br : bn);

    __shared__ float As[16][128];
    __shared__ float Bs[16][128];

    int m0 = blockIdx.x * 128;
    int n0 = blockIdx.y * 128;
    int tid = threadIdx.x;
    int txq = tid % 16, tyq = tid / 16;

    u64 acc2[4][8];
#pragma unroll
    for (int i = 0; i < 4; i++)
#pragma unroll
        for (int j = 0; j < 8; j++) acc2[i][j] = 0ull;

    for (int k0 = 0; k0 < DD; k0 += 16) {
#pragma unroll
        for (int l = 0; l < 2; l++) {
            int idx = tid + l * 256;
            int row = idx >> 2;
            int kk  = (idx & 3) * 4;
            float4 v = *(const float4*)&x[(size_t)(m0 + row) * DD + k0 + kk];
            As[kk + 0][row] = v.x; As[kk + 1][row] = v.y;
            As[kk + 2][row] = v.z; As[kk + 3][row] = v.w;
        }
#pragma unroll
        for (int l = 0; l < 2; l++) {
            int idx = tid + l * 256;
            int row = idx >> 5;
            int nn  = (idx & 31) * 4;
            *(float4*)&Bs[row][nn] = *(const float4*)&Wm[(size_t)(k0 + row) * HH + n0 + nn];
        }
        __syncthreads();
#pragma unroll
        for (int k = 0; k < 16; k++) {
            const u64* Ap = (const u64*)&As[k][tyq * 8];
            u64 ap0 = Ap[0], ap1 = Ap[1], ap2 = Ap[2], ap3 = Ap[3];
            float4 b0 = *(const float4*)&Bs[k][txq * 8];
            float4 b1 = *(const float4*)&Bs[k][txq * 8 + 4];
            u64 bs[8];
            bs[0] = splat2(b0.x); bs[1] = splat2(b0.y); bs[2] = splat2(b0.z); bs[3] = splat2(b0.w);
            bs[4] = splat2(b1.x); bs[5] = splat2(b1.y); bs[6] = splat2(b1.z); bs[7] = splat2(b1.w);
#pragma unroll
            for (int j = 0; j < 8; j++) {
                ffma2(acc2[0][j], ap0, bs[j]);
                ffma2(acc2[1][j], ap1, bs[j]);
                ffma2(acc2[2][j], ap2, bs[j]);
                ffma2(acc2[3][j], ap3, bs[j]);
            }
        }
        __syncthreads();
    }

#pragma unroll
    for (int ip = 0; ip < 4; ip++) {
#pragma unroll
        for (int half = 0; half < 2; half++) {
            int m  = m0 + tyq * 8 + ip * 2 + half;
            int bbv = m / TT;
            int tt = m % TT;
            float* outr = &g_XG[(((size_t)g * TT + tt) * BB + bbv) * HH + n0 + txq * 8];
#pragma unroll
            for (int j = 0; j < 8; j++) {
                u64 v = acc2[ip][j];
                float f = half ? __uint_as_float((unsigned)(v >> 32))
                               : __uint_as_float((unsigned)(v & 0xffffffffull));
                outr[j] = f + bias[n0 + txq * 8 + j];
            }
        }
    }
}

// ---------------------------------------------------------------------------
// Persistent GRU scan via warp-level mma.sync (bf16 hi/lo, fp32 accum).
// 128 CTAs x 8 j-cols. Warp w owns k[128w,128w+128) = 8 k-tiles; B = W^T frags
// (3 gates x 8 kt x hi/lo) resident in registers all 512 steps. h staged as
// bf16 hi/lo in 16-row chunks (= one m-tile), double-buffered cp.async;
// A frags via ldmatrix.x4. Per warp/step: 64 ldmatrix + 288 HMMA.
// Partials (8 k-slices) reduced via SMEM; epilogue exact in fp32.
// ---------------------------------------------------------------------------
__global__ __launch_bounds__(NTHR, 1) void gru_scan_mma(
    float* __restrict__ out,
    const float* __restrict__ Wzh, const float* __restrict__ Wrh, const float* __restrict__ Wnh,
    const float* __restrict__ bzh, const float* __restrict__ brh, const float* __restrict__ bnh)
{
    extern __shared__ char smem[];
    float* part = (float*)smem;                    // [w][row(64)][n(24)] stride NST
    const uint32_t sbase = smem_u32(smem);

    const int tid  = threadIdx.x;
    const int warp = tid >> 5;
    const int lane = tid & 31;
    const int jbk  = blockIdx.x;
    const int i4   = lane & 3;
    const int nfr  = lane >> 2;                    // frag n index (0..7) = j
    const int jcol_b = jbk * JB + nfr;

    // ---- B fragments in registers (held for all 512 steps) ----
    // frag: b0 = {B[k0][n], B[k0+1][n]}, b1 = {B[k0+8][n], B[k0+9][n]},
    //       k0 = kwb + kt*16 + 2*(lane&3), n = lane>>2. B[k][n] = W[k][jcol].
    unsigned bh[3][8][2], bl[3][8][2];
#pragma unroll
    for (int g = 0; g < 3; g++) {
        const float* Wg = (g == 0) ? Wzh : ((g == 1) ? Wrh : Wnh);
#pragma unroll
        for (int kt = 0; kt < 8; kt++) {
            int k0 = warp * 128 + kt * 16 + i4 * 2;
            float f0 = __ldg(&Wg[(size_t)(k0 + 0) * HH + jcol_b]);
            float f1 = __ldg(&Wg[(size_t)(k0 + 1) * HH + jcol_b]);
            float f8 = __ldg(&Wg[(size_t)(k0 + 8) * HH + jcol_b]);
            float f9 = __ldg(&Wg[(size_t)(k0 + 9) * HH + jcol_b]);
            __nv_bfloat16 h0 = __float2bfloat16(f0), h1 = __float2bfloat16(f1);
            __nv_bfloat16 h8 = __float2bfloat16(f8), h9 = __float2bfloat16(f9);
            bh[g][kt][0] = pkbf(h0, h1);
            bh[g][kt][1] = pkbf(h8, h9);
            bl[g][kt][0] = pkbf(__float2bfloat16(f0 - __bfloat162float(h0)),
                                __float2bfloat16(f1 - __bfloat162float(h1)));
            bl[g][kt][1] = pkbf(__float2bfloat16(f8 - __bfloat162float(h8)),
                                __float2bfloat16(f9 - __bfloat162float(h9)));
        }
    }

    // ---- epilogue constants: thread handles outputs tid, tid+256 ----
    int bq[2], jq[2], jc[2];
    float bzv[2], brv[2], bnv[2];
#pragma unroll
    for (int q = 0; q < 2; q++) {
        int p = tid + q * 256;
        bq[q] = p >> 3;
        jq[q] = p & 7;
        jc[q] = jbk * JB + jq[q];
        bzv[q] = __ldg(&bzh[jc[q]]);
        brv[q] = __ldg(&brh[jc[q]]);
        bnv[q] = __ldg(&bnh[jc[q]]);
    }

    // ---- zero h[0] (fp32 + bf16 splits; disjoint slices across CTAs) ----
    for (int e = tid; e < (BB * HH) / NCTA; e += NTHR) {
        int idx = blockIdx.x * ((BB * HH) / NCTA) + e;
        g_hf[0][idx] = 0.0f;
        g_hhi[0][idx] = __float2bfloat16(0.f);
        g_hlo[0][idx] = __float2bfloat16(0.f);
    }
    unsigned epoch = 1;
    grid_barrier_fast(epoch * NCTA);

    const uint32_t aoff = (uint32_t)((lane & 15) * AST + (lane >> 4) * 16);

    // stage chunk = 16 rows x 1024 halves x 2 comps = 4096 16B units; 16/thread
#define STAGE(BUF, CH) do {                                                        \
        _Pragma("unroll")                                                          \
        for (int l_ = 0; l_ < 16; l_++) {                                          \
            int idx_ = tid + l_ * NTHR;                                            \
            int comp_ = idx_ >> 11;                                                \
            int v_ = idx_ & 2047;                                                  \
            int row_ = v_ >> 7;                                                    \
            int u_ = v_ & 127;                                                     \
            const __nv_bfloat16* src_ = (comp_ ? hlo : hhi)                        \
                + (size_t)((CH) * 16 + row_) * HH + u_ * 8;                        \
            cp_async16(sbase + SM_A_OFF + (BUF) * A_BUF + comp_ * A_COMP           \
                       + row_ * AST + u_ * 16, src_);                              \
        }                                                                          \
        cp_commit();                                                               \
    } while (0)

    for (int t = 0; t < TT; t++) {
        const __nv_bfloat16* hhi = g_hhi[t & 1];
        const __nv_bfloat16* hlo = g_hlo[t & 1];
        const float* hf = g_hf[t & 1];

        // epilogue operand prefetch
        const float* xz = g_XG + ((size_t)(0 * TT + t)) * (BB * HH);
        const float* xr = g_XG + ((size_t)(1 * TT + t)) * (BB * HH);
        const float* xn = g_XG + ((size_t)(2 * TT + t)) * (BB * HH);
        float xzp[2], xrp[2], xnp[2], hpv[2];
#pragma unroll
        for (int q = 0; q < 2; q++) {
            xzp[q] = __ldg(&xz[(size_t)bq[q] * HH + jc[q]]);
            xrp[q] = __ldg(&xr[(size_t)bq[q] * HH + jc[q]]);
            xnp[q] = __ldg(&xn[(size_t)bq[q] * HH + jc[q]]);
            hpv[q] = hf[(size_t)bq[q] * HH + jc[q]];
        }

        float acc[4][3][4];
#pragma unroll
        for (int m = 0; m < 4; m++)
#pragma unroll
            for (int g = 0; g < 3; g++)
#pragma unroll
                for (int c = 0; c < 4; c++) acc[m][g][c] = 0.0f;

        STAGE(0, 0);
        for (int ch = 0; ch < 4; ch++) {
            if (ch + 1 < 4) { STAGE((ch + 1) & 1, ch + 1); cp_wait<1>(); }
            else            { cp_wait<0>(); }
            __syncthreads();     // chunk ch visible

            const uint32_t abh = sbase + SM_A_OFF + (ch & 1) * A_BUF + aoff + warp * 256;
            const uint32_t abl = abh + A_COMP;
#pragma unroll
            for (int kt = 0; kt < 8; kt++) {
                unsigned ah[4], al[4];
                ldmat4(ah, abh + kt * 32);
                ldmat4(al, abl + kt * 32);
#pragma unroll
                for (int g = 0; g < 3; g++) {
                    mma_bf16(acc[ch][g], ah, bh[g][kt]);
                    mma_bf16(acc[ch][g], ah, bl[g][kt]);
                    mma_bf16(acc[ch][g], al, bh[g][kt]);
                }
            }
            __syncthreads();     // buffer free for chunk ch+2
        }

        // ---- store k-slice partials: c frag rows = lane>>2 (+8), cols 2*(lane&3) ----
        {
            int r0 = lane >> 2, c0 = (lane & 3) * 2;
#pragma unroll
            for (int m = 0; m < 4; m++)
#pragma unroll
                for (int g = 0; g < 3; g++) {
                    float* p0 = part + warp * WSTR + (m * 16 + r0) * NST + g * 8 + c0;
                    *(float2*)p0 = make_float2(acc[m][g][0], acc[m][g][1]);
                    *(float2*)(p0 + 8 * NST) = make_float2(acc[m][g][2], acc[m][g][3]);
                }
        }
        __syncthreads();

        // ---- reduce 8 k-slices + gate epilogue (2 outputs per thread) ----
#pragma unroll
        for (int q = 0; q < 2; q++) {
            int o = bq[q] * NST + jq[q];
            float sz = 0.0f, sr = 0.0f, sn = 0.0f;
#pragma unroll
            for (int w = 0; w < 8; w++) {
                sz += part[w * WSTR + o];
                sr += part[w * WSTR + o + 8];
                sn += part[w * WSTR + o + 16];
            }
            float z = 1.0f / (1.0f + __expf(-(xzp[q] + sz + bzv[q])));
            float r = 1.0f / (1.0f + __expf(-(xrp[q] + sr + brv[q])));
            float n = tanhf(xnp[q] + r * (sn + bnv[q]));
            float hnew = (1.0f - z) * n + z * hpv[q];
            if (t == TT - 1) {
                out[(size_t)bq[q] * HH + jc[q]] = hnew;
            } else {
                size_t idx = (size_t)bq[q] * HH + jc[q];
                g_hf[(t + 1) & 1][idx] = hnew;
                __nv_bfloat16 hi = __float2bfloat16(hnew);
                __nv_bfloat16 lo = __float2bfloat16(hnew - __bfloat162float(hi));
                stcg_u16(&g_hhi[(t + 1) & 1][idx], hi);
                stcg_u16(&g_hlo[(t + 1) & 1][idx], lo);
            }
        }

        if (t != TT - 1) { ++epoch; grid_barrier_fast(epoch * NCTA); }
    }
#undef STAGE
}

// ---------------------------------------------------------------------------
extern "C" void kernel_launch(void* const* d_in, const int* in_sizes, int n_in,
                              void* d_out, int out_size) {
    const float* x    = (const float*)d_in[0];
    const float* W_zx = (const float*)d_in[1];
    const float* W_zh = (const float*)d_in[2];
    const float* W_rx = (const float*)d_in[3];
    const float* W_rh = (const float*)d_in[4];
    const float* W_nx = (const float*)d_in[5];
    const float* W_nh = (const float*)d_in[6];
    const float* b_zx = (const float*)d_in[7];
    const float* b_zh = (const float*)d_in[8];
    const float* b_rx = (const float*)d_in[9];
    const float* b_rh = (const float*)d_in[10];
    const float* b_nx = (const float*)d_in[11];
    const float* b_nh = (const float*)d_in[12];
    float* out = (float*)d_out;

    cudaFuncSetAttribute(gru_scan_mma,
                         cudaFuncAttributeMaxDynamicSharedMemorySize, SCAN_SMEM);

    reset_kernel<<<1, 32>>>();
    xproj_kernel<<<dim3((BB * TT) / 128, HH / 128, 3), 256>>>(
        x, W_zx, W_rx, W_nx, b_zx, b_rx, b_nx);
    gru_scan_mma<<<NCTA, NTHR, SCAN_SMEM>>>(
        out, W_zh, W_rh, W_nh, b_zh, b_rh, b_nh);
}